// round 16
// baseline (speedup 1.0000x reference)
#include <cuda_runtime.h>
#include <cuda_fp16.h>
#include <stdint.h>

// Problem constants
#define NTOK 2048      // B*S = 2*1024
#define HID  1024
#define NEXP 8
#define VOC  32000
#define KVC  2048
#define LSCALE 0.25f   // ALPHA / RANK

// ---------------- scratch (device globals; no allocations) ----------------
__device__ __half g_hbuf[NTOK * HID];             // fp16 embedded tokens   4 MB
__device__ __half g_wmod[NEXP * HID * HID];       // fp16 (W+la@lb*s)^T    16 MB [e][f][h]
__device__ float  g_cvec[NEXP * HID];             // cache_vec + expert_b
__device__ float  g_partial[2 * NTOK * HID];      // per-slot outputs      16 MB
__device__ __half g_abuf[NTOK * HID];             // fp16(p0+p1)            4 MB
__device__ __half g_w16[(size_t)VOC * HID];       // fp16(vocab_w), SAME [k][n] layout  64 MB
__device__ int    g_count[NEXP];                  // zero-init at load; reset by k_aprep
__device__ unsigned int g_plist[NEXP * NTOK];     // token | slot<<16
__device__ float  g_pw[NEXP * NTOK];
__device__ unsigned char g_self[NEXP * KVC];
__device__ float  g_msum_part[NEXP * 16 * HID];

__device__ __forceinline__ uint32_t smem_u32(const void* p) {
    uint32_t a;
    asm("{ .reg .u64 t; cvta.to.shared.u64 t, %1; cvt.u32.u64 %0, t; }" : "=r"(a) : "l"(p));
    return a;
}
__device__ __forceinline__ void cp16(uint32_t dst, const void* src) {
    asm volatile("cp.async.cg.shared.global [%0], [%1], 16;" :: "r"(dst), "l"(src) : "memory");
}
#define CP_COMMIT() asm volatile("cp.async.commit_group;" ::: "memory")
#define CP_WAIT1()  asm volatile("cp.async.wait_group 1;" ::: "memory")
#define CP_WAIT0()  asm volatile("cp.async.wait_group 0;" ::: "memory")

#define LDMX4(a0,a1,a2,a3,addr) \
    asm volatile("ldmatrix.sync.aligned.m8n8.x4.shared.b16 {%0,%1,%2,%3}, [%4];" \
        : "=r"(a0), "=r"(a1), "=r"(a2), "=r"(a3) : "r"(addr))
#define LDMX2(b0,b1,addr) \
    asm volatile("ldmatrix.sync.aligned.m8n8.x2.shared.b16 {%0,%1}, [%2];" \
        : "=r"(b0), "=r"(b1) : "r"(addr))
#define LDMX2T(b0,b1,addr) \
    asm volatile("ldmatrix.sync.aligned.m8n8.x2.trans.shared.b16 {%0,%1}, [%2];" \
        : "=r"(b0), "=r"(b1) : "r"(addr))
#define MMA_F16(d, A0,A1,A2,A3, B0,B1) \
    asm volatile("mma.sync.aligned.m16n8k16.row.col.f32.f16.f16.f32 " \
        "{%0,%1,%2,%3}, {%4,%5,%6,%7}, {%8,%9}, {%0,%1,%2,%3};" \
        : "+f"((d)[0]), "+f"((d)[1]), "+f"((d)[2]), "+f"((d)[3]) \
        : "r"(A0), "r"(A1), "r"(A2), "r"(A3), "r"(B0), "r"(B1))

// ---------------- k_prep: fused select | wmodT | route | w16-convert ----------------
// flattened grid: [0,8) select, [8,2056) wmodT, [2056,4104) route, [4104,12104) w16
#define PREP_SEL0   0
#define PREP_WMOD0  8
#define PREP_ROUTE0 (PREP_WMOD0 + 2048)
#define PREP_WT0    (PREP_ROUTE0 + NTOK)
#define PREP_BLOCKS (PREP_WT0 + 8000)

// Shared-memory union: personas never overlap within a block -> max, not sum.
union PrepSm {
    float ts[64][65];                                    // wmodT       (16.6 KB)
    struct { unsigned int sv[KVC]; int redi[256]; } sel; // select      ( 9.2 KB)
    struct { float hs[HID]; float sred[8][8]; } rt;      // route       ( 4.3 KB)
};

__global__ void __launch_bounds__(256) k_prep(
    const float* __restrict__ ew, const float* __restrict__ la, const float* __restrict__ lb,
    const float* __restrict__ imp,
    const int* __restrict__ x, const float* __restrict__ emb,
    const float* __restrict__ gw, const float* __restrict__ gb,
    const float* __restrict__ vw)
{
    __shared__ PrepSm sm;

    int bid = blockIdx.x;
    int tid = threadIdx.x;

    if (bid >= PREP_WT0) {
        // ===== w16: streaming fp32->fp16 convert of vocab_w (layout preserved) =====
        size_t base = (size_t)(bid - PREP_WT0) * 4096;
        #pragma unroll
        for (int it = 0; it < 2; it++) {
            size_t off = base + (size_t)it * 2048 + (size_t)tid * 8;
            float4 v0 = *(const float4*)(vw + off);
            float4 v1 = *(const float4*)(vw + off + 4);
            __half2 h0 = __floats2half2_rn(v0.x, v0.y);
            __half2 h1 = __floats2half2_rn(v0.z, v0.w);
            __half2 h2 = __floats2half2_rn(v1.x, v1.y);
            __half2 h3 = __floats2half2_rn(v1.z, v1.w);
            uint4 o;
            o.x = *(uint32_t*)&h0; o.y = *(uint32_t*)&h1;
            o.z = *(uint32_t*)&h2; o.w = *(uint32_t*)&h3;
            *(uint4*)(g_w16 + off) = o;
        }
    } else if (bid < PREP_WMOD0) {
        // ===== k_select (block = expert) =====
        int e = bid;
        int n = KVC - 128 * e;
        int k = n / 2;
        unsigned int* sv = sm.sel.sv;
        int* redi = sm.sel.redi;
        for (int i = tid; i < n; i += 256) sv[i] = __float_as_uint(imp[e * KVC + i]);
        __syncthreads();
        unsigned int T = 0;
        for (int bit = 31; bit >= 0; --bit) {
            unsigned int cand = T | (1u << bit);
            int c = 0;
            for (int i = tid; i < n; i += 256) c += (sv[i] >= cand);
            redi[tid] = c; __syncthreads();
            for (int s = 128; s > 0; s >>= 1) { if (tid < s) redi[tid] += redi[tid + s]; __syncthreads(); }
            int cnt = redi[0];
            __syncthreads();
            if (cnt >= k) T = cand;
        }
        int c = 0;
        for (int i = tid; i < n; i += 256) c += (sv[i] > T);
        redi[tid] = c; __syncthreads();
        for (int s = 128; s > 0; s >>= 1) { if (tid < s) redi[tid] += redi[tid + s]; __syncthreads(); }
        int g = redi[0];
        __syncthreads();
        for (int i = tid; i < n; i += 256) g_self[e * KVC + i] = (sv[i] > T) ? 1 : 0;
        __syncthreads();
        if (tid == 0) {
            int extra = k - g;
            for (int i = 0; i < n && extra > 0; i++) {
                if (sv[i] == T) { g_self[e * KVC + i] = 1; extra--; }
            }
        }
    } else if (bid < PREP_ROUTE0) {
        // ===== k_wmodT: g_wmod[e][f][h] = fp16(ew[e][h][f] + s*la@lb) =====
        int b = bid - PREP_WMOD0;
        int e = b >> 8;                      // /256
        int n0 = (b & 15) * 64;              // f tile
        int k0 = ((b >> 4) & 15) * 64;       // h tile
        const float* lbe = lb + (size_t)e * 4 * HID;
        #pragma unroll
        for (int r = 0; r < 16; r++) {
            int idx = tid + r * 256;
            int kk = idx / 64, nn = idx % 64;
            int h = k0 + kk, f = n0 + nn;
            const float* lar = la + ((size_t)e * HID + h) * 4;
            float v = ew[((size_t)e * HID + h) * HID + f]
                    + LSCALE * (lar[0] * lbe[f] + lar[1] * lbe[HID + f]
                               + lar[2] * lbe[2 * HID + f] + lar[3] * lbe[3 * HID + f]);
            sm.ts[kk][nn] = v;
        }
        __syncthreads();
        #pragma unroll
        for (int r = 0; r < 8; r++) {
            int idx = tid + r * 256;
            int nn = idx >> 5, kp = idx & 31;
            __half2 hp = __floats2half2_rn(sm.ts[kp * 2][nn], sm.ts[kp * 2 + 1][nn]);
            *(__half2*)(g_wmod + ((size_t)e * HID + n0 + nn) * HID + k0 + kp * 2) = hp;
        }
    } else {
        // ===== k_route (block = token) =====
        int t = bid - PREP_ROUTE0;
        const float* er = emb + (size_t)x[t] * HID;
        float* hs = sm.rt.hs;
        float4* hs4 = (float4*)hs;
        __half2* hb2 = (__half2*)(g_hbuf + (size_t)t * HID);
        for (int i = tid; i < HID / 4; i += 256) {
            float4 v = ((const float4*)er)[i];
            hs4[i] = v;
            hb2[2 * i]     = __floats2half2_rn(v.x, v.y);
            hb2[2 * i + 1] = __floats2half2_rn(v.z, v.w);
        }
        __syncthreads();
        float p[8] = {0.f, 0.f, 0.f, 0.f, 0.f, 0.f, 0.f, 0.f};
        for (int i = tid; i < HID; i += 256) {
            float hv = hs[i];
            const float* g = gw + (size_t)i * 8;
            #pragma unroll
            for (int e2 = 0; e2 < 8; e2++) p[e2] += hv * g[e2];
        }
        #pragma unroll
        for (int off = 16; off > 0; off >>= 1)
            #pragma unroll
            for (int e2 = 0; e2 < 8; e2++) p[e2] += __shfl_down_sync(0xffffffffu, p[e2], off);
        int warp = tid / 32, lane = tid % 32;
        if (lane == 0)
            #pragma unroll
            for (int e2 = 0; e2 < 8; e2++) sm.rt.sred[e2][warp] = p[e2];
        __syncthreads();
        if (tid == 0) {
            float lg[8];
            #pragma unroll
            for (int e2 = 0; e2 < 8; e2++) {
                float s = 0.f;
                #pragma unroll
                for (int w = 0; w < 8; w++) s += sm.rt.sred[e2][w];
                lg[e2] = s + gb[e2];
            }
            int i1 = 0;
            #pragma unroll
            for (int e2 = 1; e2 < 8; e2++) if (lg[e2] > lg[i1]) i1 = e2;
            int i2 = -1;
            #pragma unroll
            for (int e2 = 0; e2 < 8; e2++) {
                if (e2 == i1) continue;
                if (i2 < 0 || lg[e2] > lg[i2]) i2 = e2;
            }
            float w1 = 1.f / (1.f + expf(lg[i2] - lg[i1]));
            float w2 = 1.f - w1;
            int p1 = atomicAdd(&g_count[i1], 1);
            g_plist[i1 * NTOK + p1] = (unsigned)t;
            g_pw[i1 * NTOK + p1] = w1;
            int p2 = atomicAdd(&g_count[i2], 1);
            g_plist[i2 * NTOK + p2] = (unsigned)t | (1u << 16);
            g_pw[i2 * NTOK + p2] = w2;
        }
    }
}

// ---------------- k2b: masked column partial sums (branchless, 16-way z-split) ----------------
// grid (HID/256, NEXP, 16), block 256
__global__ void k_sumsel(const float* __restrict__ cv) {
    int e = blockIdx.y, z = blockIdx.z;
    int col = blockIdx.x * 256 + threadIdx.x;
    int n = KVC - 128 * e;
    int r0 = z * 128;
    float* outp = g_msum_part + (size_t)(e * 16 + z) * HID + col;
    if (r0 >= n) { *outp = 0.f; return; }
    int cntr = min(128, n - r0);
    __shared__ float fm[128];
    if (threadIdx.x < 128)
        fm[threadIdx.x] = (threadIdx.x < cntr) ? (float)g_self[e * KVC + r0 + threadIdx.x] : 0.f;
    __syncthreads();
    float acc = 0.f;
    const float* base = cv + (size_t)e * KVC * HID + (size_t)r0 * HID + col;
    #pragma unroll 8
    for (int i = 0; i < 128; i++) {
        if (i < cntr) acc = fmaf(fm[i], base[(size_t)i * HID], acc);
    }
    *outp = acc;
}

// ---------------- k2c: cache vec = m + (m@la)@lb*s + expert_b ----------------
__global__ void k_cvec(const float* __restrict__ la, const float* __restrict__ lb,
                       const float* __restrict__ eb) {
    int e = blockIdx.x, tid = threadIdx.x;
    __shared__ float m[HID];
    __shared__ float red[4 * 256];
    int k = (KVC - 128 * e) / 2;
    float invk = 1.f / (float)k;
    for (int f = tid; f < HID; f += 256) {
        float s = 0.f;
        #pragma unroll
        for (int z = 0; z < 16; z++) s += g_msum_part[(size_t)(e * 16 + z) * HID + f];
        m[f] = s * invk;
    }
    __syncthreads();
    float u[4] = {0.f, 0.f, 0.f, 0.f};
    for (int f = tid; f < HID; f += 256) {
        float mv = m[f];
        const float* lr = la + ((size_t)e * HID + f) * 4;
        u[0] += mv * lr[0]; u[1] += mv * lr[1]; u[2] += mv * lr[2]; u[3] += mv * lr[3];
    }
    #pragma unroll
    for (int r = 0; r < 4; r++) red[r * 256 + tid] = u[r];
    __syncthreads();
    for (int s = 128; s > 0; s >>= 1) {
        if (tid < s)
            #pragma unroll
            for (int r = 0; r < 4; r++) red[r * 256 + tid] += red[r * 256 + tid + s];
        __syncthreads();
    }
    float u0 = red[0], u1 = red[256], u2 = red[512], u3 = red[768];
    const float* lbe = lb + (size_t)e * 4 * HID;
    for (int f = tid; f < HID; f += 256) {
        g_cvec[e * HID + f] = m[f]
            + LSCALE * (u0 * lbe[f] + u1 * lbe[HID + f] + u2 * lbe[2 * HID + f] + u3 * lbe[3 * HID + f])
            + eb[e * HID + f];
    }
}

// ---------------- k_egemm3: per-expert gathered fp16 mma GEMM, 128x128 tile ----------------
// grid (HID/128=8, NTOK/128=16, NEXP), block 256 (8 warps = 2m x 4n, warp tile 64x32)
__global__ void __launch_bounds__(256, 2) k_egemm3() {
    extern __shared__ float esm[];
    __shared__ unsigned int stok[128];
    __shared__ float swt[128];

    int e = blockIdx.z;
    int cnt = g_count[e];
    int m0 = blockIdx.y * 128;
    if (m0 >= cnt) return;
    int n0 = blockIdx.x * 128;

    int tid = threadIdx.x;
    int lane = tid & 31, wid = tid >> 5;
    int wm = wid >> 2, wn = wid & 3;
    uint32_t sbase = smem_u32(esm);

    if (tid < 128) {
        int p = m0 + tid;
        if (p < cnt) { stok[tid] = g_plist[e * NTOK + p]; swt[tid] = g_pw[e * NTOK + p]; }
        else         { stok[tid] = 0u;                    swt[tid] = 0.f; }
    }
    __syncthreads();

    const __half* wmT = g_wmod + (size_t)e * HID * HID;

#define EG_ISSUE(STAGE, BUF) do {                                              \
    int k0 = (STAGE) * 64;                                                     \
    _Pragma("unroll") for (int j = 0; j < 4; j++) {                            \
        int idx = tid + j * 256;                                               \
        int row = idx >> 3, slot = idx & 7;                                    \
        uint32_t so = (uint32_t)(row * 128 + ((slot ^ (row & 7)) << 4));       \
        int tok = (int)(stok[row] & 0xffffu);                                  \
        cp16(sbase + (uint32_t)(BUF) * 32768u + so,                            \
             g_hbuf + (size_t)tok * HID + k0 + slot * 8);                      \
        cp16(sbase + 16384u + (uint32_t)(BUF) * 32768u + so,                   \
             wmT + (size_t)(n0 + row) * HID + k0 + slot * 8);                  \
    }                                                                          \
    CP_COMMIT();                                                               \
} while (0)

    float acc[16][4];
    #pragma unroll
    for (int i = 0; i < 16; i++) { acc[i][0]=0.f; acc[i][1]=0.f; acc[i][2]=0.f; acc[i][3]=0.f; }

    int tileA = lane >> 3;
    int rlA   = ((tileA & 1) << 3) + (lane & 7);
    int thiA  = tileA >> 1;
    int r7A   = lane & 7;
    uint32_t aRowByte = (uint32_t)((wm * 64 + rlA) * 128);
    int l16 = lane & 15;
    int tB  = l16 >> 3;
    int rlB = l16 & 7;
    uint32_t bRowByte = (uint32_t)((wn * 32 + rlB) * 128);

    const int NST = HID / 64;                      // 16 chunks
    EG_ISSUE(0, 0);
    EG_ISSUE(1, 1);
    int buf = 0;
    for (int s = 0; s < NST; s++) {
        if (s + 1 < NST) CP_WAIT1(); else CP_WAIT0();
        __syncthreads();
        if (s + 2 < NST) {
            int nb = buf + 2; if (nb >= 3) nb -= 3;
            EG_ISSUE(s + 2, nb);
        }
        uint32_t Ab = sbase + (uint32_t)buf * 32768u;
        uint32_t Bb = Ab + 16384u;
        #pragma unroll
        for (int ks = 0; ks < 4; ks++) {
            uint32_t b0[4], b1[4];
            #pragma unroll
            for (int nt = 0; nt < 4; nt++) {
                uint32_t addr = Bb + bRowByte + (uint32_t)(nt * 1024)
                              + (uint32_t)(((ks * 2 + tB) ^ rlB) << 4);
                LDMX2(b0[nt], b1[nt], addr);
            }
            #pragma unroll
            for (int mt = 0; mt < 4; mt++) {
                uint32_t a0, a1, a2, a3;
                uint32_t addr = Ab + aRowByte + (uint32_t)(mt * 2048)
                              + (uint32_t)(((ks * 2 + thiA) ^ r7A) << 4);
                LDMX4(a0, a1, a2, a3, addr);
                #pragma unroll
                for (int nt = 0; nt < 4; nt++)
                    MMA_F16(acc[mt * 4 + nt], a0, a1, a2, a3, b0[nt], b1[nt]);
            }
        }
        buf++; if (buf >= 3) buf -= 3;
    }

    // epilogue: out[slot][tok][n] = w * (acc + cvec)
    int rr = lane >> 2, cc = (lane & 3) * 2;
    #pragma unroll
    for (int mt = 0; mt < 4; mt++) {
        #pragma unroll
        for (int half = 0; half < 2; half++) {
            int ml = wm * 64 + mt * 16 + rr + half * 8;
            if (m0 + ml >= cnt) continue;
            unsigned int pk = stok[ml];
            int tok = (int)(pk & 0xffffu), slot = (int)(pk >> 16);
            float w = swt[ml];
            float* outp = g_partial + (size_t)slot * NTOK * HID + (size_t)tok * HID;
            #pragma unroll
            for (int nt = 0; nt < 4; nt++) {
                int n = n0 + wn * 32 + nt * 8 + cc;
                const float* d = acc[mt * 4 + nt];
                float cv0 = g_cvec[e * HID + n], cv1 = g_cvec[e * HID + n + 1];
                float2 o;
                o.x = w * (d[half * 2 + 0] + cv0);
                o.y = w * (d[half * 2 + 1] + cv1);
                *(float2*)(outp + n) = o;
            }
        }
    }
#undef EG_ISSUE
}

// ---------------- k_aprep: A = fp16(p0 + p1); also resets g_count for next call ----------------
__global__ void k_aprep() {
    int m = blockIdx.x;
    if (m == 0 && threadIdx.x < NEXP) g_count[threadIdx.x] = 0;
    const float4* p0 = (const float4*)(g_partial + (size_t)m * HID);
    const float4* p1 = (const float4*)(g_partial + (size_t)NTOK * HID + (size_t)m * HID);
    __half2* a2 = (__half2*)(g_abuf + (size_t)m * HID);
    int i = threadIdx.x;
    float4 v0 = p0[i], v1 = p1[i];
    a2[2 * i]     = __floats2half2_rn(v0.x + v1.x, v0.y + v1.y);
    a2[2 * i + 1] = __floats2half2_rn(v0.z + v1.z, v0.w + v1.w);
}

// ---------------- k_vgemm3: fp16 mma GEMM, 128x128 tile, 3-stage cp.async ----------------
// B read DIRECTLY from g_w16 [k][n] layout; fragments via ldmatrix.trans.
// grid (NTOK/128=16, VOC/128=250), block 256 (8 warps = 2m x 4n, warp tile 64x32)
// smem: 3 stages x (A[128 m][64 k] 16KB, 128B rows + B[64 k][128 n] 16KB, 256B rows)
__global__ void __launch_bounds__(256, 2) k_vgemm3(const float* __restrict__ vb,
                                                   float* __restrict__ out) {
    extern __shared__ float vsm[];
    int tid = threadIdx.x;
    int lane = tid & 31, wid = tid >> 5;
    int wm = wid >> 2, wn = wid & 3;
    int m0 = blockIdx.x * 128, n0 = blockIdx.y * 128;
    const __half* Ag = g_abuf + (size_t)m0 * HID;
    const __half* Wg = g_w16;                      // [k][n] = [HID][VOC]
    uint32_t sbase = smem_u32(vsm);

#define VG_ISSUE(STAGE, BUF) do {                                              \
    int k0 = (STAGE) * 64;                                                     \
    _Pragma("unroll") for (int j = 0; j < 4; j++) {                            \
        int idx = tid + j * 256;                                               \
        int rowA = idx >> 3, slotA = idx & 7;                                  \
        cp16(sbase + (uint32_t)(BUF) * 32768u                                  \
                 + (uint32_t)(rowA * 128 + ((slotA ^ (rowA & 7)) << 4)),       \
             Ag + (size_t)rowA * HID + k0 + slotA * 8);                        \
        int rowB = idx >> 4, slotB = idx & 15;                                 \
        cp16(sbase + 16384u + (uint32_t)(BUF) * 32768u                         \
                 + (uint32_t)(rowB * 256 + ((slotB ^ (rowB & 15)) << 4)),      \
             Wg + (size_t)(k0 + rowB) * VOC + n0 + slotB * 8);                 \
    }                                                                          \
    CP_COMMIT();                                                               \
} while (0)

    float acc[16][4];
    #pragma unroll
    for (int i = 0; i < 16; i++) { acc[i][0]=0.f; acc[i][1]=0.f; acc[i][2]=0.f; acc[i][3]=0.f; }

    int tileA = lane >> 3;
    int rlA   = ((tileA & 1) << 3) + (lane & 7);
    int thiA  = tileA >> 1;
    int r7A   = lane & 7;
    uint32_t aRowByte = (uint32_t)((wm * 64 + rlA) * 128);
    int l16 = lane & 15;                           // B: k-row provider lane
    uint32_t bRowByte = (uint32_t)(l16 * 256);
    int bSlotBase = wn * 4;                        // 16B slot = 8 n-halves

    const int NST = HID / 64;                      // 16 chunks
    VG_ISSUE(0, 0);
    VG_ISSUE(1, 1);
    int buf = 0;                                   // buf = s % 3
    for (int s = 0; s < NST; s++) {
        if (s + 1 < NST) CP_WAIT1(); else CP_WAIT0();
        __syncthreads();                           // stage s ready + all warps done with s-1
        if (s + 2 < NST) {
            int nb = buf + 2; if (nb >= 3) nb -= 3;
            VG_ISSUE(s + 2, nb);                   // overwrites buffer of stage s-1 (safe)
        }
        uint32_t Ab = sbase + (uint32_t)buf * 32768u;
        uint32_t Bb = Ab + 16384u;
        #pragma unroll
        for (int ks = 0; ks < 4; ks++) {
            uint32_t b0[4], b1[4];
            #pragma unroll
            for (int nt = 0; nt < 4; nt++) {
                // rows = k (ks*16 + l16), 256B apart; slot swizzle ^ (row & 15) = ^ l16
                uint32_t addr = Bb + (uint32_t)(ks * 4096) + bRowByte
                              + (uint32_t)(((bSlotBase + nt) ^ l16) << 4);
                LDMX2T(b0[nt], b1[nt], addr);
            }
            #pragma unroll
            for (int mt = 0; mt < 4; mt++) {
                uint32_t a0, a1, a2, a3;
                uint32_t addr = Ab + aRowByte + (uint32_t)(mt * 2048)
                              + (uint32_t)(((ks * 2 + thiA) ^ r7A) << 4);
                LDMX4(a0, a1, a2, a3, addr);
                #pragma unroll
                for (int nt = 0; nt < 4; nt++)
                    MMA_F16(acc[mt * 4 + nt], a0, a1, a2, a3, b0[nt], b1[nt]);
            }
        }
        buf++; if (buf >= 3) buf -= 3;
    }

    // epilogue
    int rr = lane >> 2, cc = (lane & 3) * 2;
    #pragma unroll
    for (int mt = 0; mt < 4; mt++) {
        int m = m0 + wm * 64 + mt * 16 + rr;
        #pragma unroll
        for (int nt = 0; nt < 4; nt++) {
            int n = n0 + wn * 32 + nt * 8 + cc;
            const float* d = acc[mt * 4 + nt];
            float2 bb = *(const float2*)(vb + n);
            float2 o0 = make_float2(d[0] + bb.x, d[1] + bb.y);
            float2 o1 = make_float2(d[2] + bb.x, d[3] + bb.y);
            *(float2*)(out + (size_t)m * VOC + n) = o0;
            *(float2*)(out + (size_t)(m + 8) * VOC + n) = o1;
        }
    }
#undef VG_ISSUE
}

// ---------------- launch ----------------
extern "C" void kernel_launch(void* const* d_in, const int* in_sizes, int n_in,
                              void* d_out, int out_size) {
    const int*   x    = (const int*)  d_in[0];
    const float* emb  = (const float*)d_in[1];
    const float* gw   = (const float*)d_in[2];
    const float* gb   = (const float*)d_in[3];
    const float* ew   = (const float*)d_in[4];
    const float* eb   = (const float*)d_in[5];
    const float* ela  = (const float*)d_in[6];
    const float* elb  = (const float*)d_in[7];
    const float* cv   = (const float*)d_in[8];
    const float* cimp = (const float*)d_in[9];
    const float* cla  = (const float*)d_in[10];
    const float* clb  = (const float*)d_in[11];
    const float* vw   = (const float*)d_in[12];
    const float* vb   = (const float*)d_in[13];
    float* out = (float*)d_out;

    cudaFuncSetAttribute(k_egemm3, cudaFuncAttributeMaxDynamicSharedMemorySize, 98304);
    cudaFuncSetAttribute(k_vgemm3, cudaFuncAttributeMaxDynamicSharedMemorySize, 98304);

    k_prep<<<PREP_BLOCKS, 256>>>(ew, ela, elb, cimp, x, emb, gw, gb, vw);
    k_sumsel<<<dim3(HID / 256, NEXP, 16), 256>>>(cv);
    k_cvec<<<NEXP, 256>>>(cla, clb, eb);
    k_egemm3<<<dim3(HID / 128, NTOK / 128, NEXP), 256, 98304>>>();
    k_aprep<<<NTOK, 256>>>();
    k_vgemm3<<<dim3(NTOK / 128, VOC / 128), 256, 98304>>>(vb, out);
}